// round 16
// baseline (speedup 1.0000x reference)
#include <cuda_runtime.h>
#include <math.h>
#include <stdint.h>

#define NN 50000
#define FF 128
#define CC 512
#define EE 800000
#define HH 256

// Output layout: new_x [C,F], new_adj [C,C], new_batch [C], S [N,C]
#define OFF_ADJ   (CC*FF)
#define OFF_BATCH (OFF_ADJ + CC*CC)
#define OFF_S     (OFF_BATCH + CC)

#define EB ((EE + 255) / 256)
#define HSB ((NN * 32 + 255) / 256)
#define INITB 512

// weight split offsets (elements)
#define WOFF1 0
#define WOFF2 (FF*HH)
#define WOFF3 (WOFF2 + HH*HH)
#define WTOT  (WOFF3 + HH*CC)

// ---------------- scratch ----------------------------------------------------
__device__ __align__(16) float    g_h[(size_t)NN * CC];     // gemm float outputs
__device__ __align__(16) uint32_t g_ah[(size_t)NN * HH];    // activation hi (tf32)
__device__ __align__(16) uint32_t g_al[(size_t)NN * HH];    // activation lo (tf32)
__device__ __align__(16) uint32_t g_wh[WTOT];
__device__ __align__(16) uint32_t g_wl[WTOT];
__device__ float g_inv[NN];
__device__ int   g_deg[NN];
__device__ int   g_off[NN + 1];
__device__ int   g_cur[NN];
__device__ int   g_csr_src[EE];
__device__ float g_csr_cf[EE];
__device__ int   g_cluster[NN];
__device__ float g_hs[NN];
__device__ int   g_sdeg[NN];
__device__ float g_invs[NN];
__device__ float g_sagg[NN];
__device__ float g_score[NN];
__device__ int   g_icnt[CC];
__device__ int   g_segkey[CC];
__device__ int   g_segidx[CC];

__device__ __forceinline__ int fkey(float f) {
    int b = __float_as_int(f);
    return b < 0 ? (b ^ 0x7FFFFFFF) : b;
}
__device__ __forceinline__ float fdec(int k) {
    return __int_as_float(k < 0 ? (k ^ 0x7FFFFFFF) : k);
}
__device__ __forceinline__ uint32_t f2tf(float f) {
    uint32_t r;
    asm("cvt.rna.tf32.f32 %0, %1;" : "=r"(r) : "f"(f));
    return r;
}

// ---------------- fused init + g_deg zero ------------------------------------
__global__ void k_initdeg(float* out) {
    int bid = blockIdx.x;
    int t = threadIdx.x;
    if (bid < INITB) {
        int i = bid * 256 + t;
        int stride = INITB * 256;
        for (int j = i; j < NN; j += stride) { g_sdeg[j] = 0; g_sagg[j] = 0.f; }
        for (int j = i; j < CC; j += stride) {
            g_icnt[j] = 0; g_segkey[j] = (int)0x80000000; g_segidx[j] = NN;
            out[OFF_BATCH + j] = 0.f;
        }
        for (int j = i; j < CC * CC; j += stride) out[OFF_ADJ + j] = 0.f;
    } else {
        int zi = (bid - INITB) * 256 + t;
        if (zi < NN) g_deg[zi] = 0;
    }
}

__global__ void k_deg(const int* __restrict__ ei) {
    int e = blockIdx.x * blockDim.x + threadIdx.x;
    if (e < EE) atomicAdd(&g_deg[ei[EE + e]], 1);
}

// single block: exclusive scan + inv + cur
__global__ void __launch_bounds__(1024) k_scan() {
    __shared__ int ssum[1024];
    int t = threadIdx.x;
    const int chunk = (NN + 1023) / 1024;
    int b = t * chunk, e = min(b + chunk, NN);
    int s = 0;
    for (int i = b; i < e; i++) s += g_deg[i];
    ssum[t] = s;
    __syncthreads();
    for (int off = 1; off < 1024; off <<= 1) {
        int v = (t >= off) ? ssum[t - off] : 0;
        __syncthreads();
        ssum[t] += v;
        __syncthreads();
    }
    int run = (t > 0) ? ssum[t - 1] : 0;
    for (int i = b; i < e; i++) {
        int d = g_deg[i];
        g_off[i] = run;
        g_cur[i] = run;
        g_inv[i] = rsqrtf((float)d + 1.0f);
        run += d;
    }
    if (t == 1023) g_off[NN] = ssum[1023];
}

__global__ void k_fill(const int* __restrict__ ei) {
    int e = blockIdx.x * blockDim.x + threadIdx.x;
    if (e >= EE) return;
    int s = ei[e], d = ei[EE + e];
    int p = atomicAdd(&g_cur[d], 1);
    g_csr_src[p] = s;
    g_csr_cf[p] = g_inv[s] * g_inv[d];
}

// ---------------- weight pre-split (tf32 hi/lo) ------------------------------
__global__ void k_wsplit(const float* __restrict__ W1,
                         const float* __restrict__ W2,
                         const float* __restrict__ W3,
                         uint32_t* __restrict__ wh,
                         uint32_t* __restrict__ wl) {
    int i = blockIdx.x * 256 + threadIdx.x;
    if (i >= WTOT) return;
    float v;
    if (i < WOFF2)      v = W1[i - WOFF1];
    else if (i < WOFF3) v = W2[i - WOFF2];
    else                v = W3[i - WOFF3];
    uint32_t h = f2tf(v);
    wh[i] = h;
    wl[i] = f2tf(v - __uint_as_float(h));
}

// ---------------- aggregation: 128-wide slice, writes split tf32 -------------
// Same accumulation math as prior rounds; epilogue stores (hi, lo) pair,
// replicating bit-exactly the conversion formerly done in the GEMM loader.
template <int STRIDE>
__global__ void __launch_bounds__(128) k_aggs(const float* __restrict__ h,
                                              uint32_t* __restrict__ ah,
                                              uint32_t* __restrict__ al,
                                              int foff) {
    int t = threadIdx.x;
    const float* hf = h + foff + t;
    for (int i = blockIdx.x; i < NN; i += gridDim.x) {
        int beg = g_off[i], end = g_off[i + 1];
        float inv = g_inv[i];
        float acc0 = inv * inv * __ldg(hf + (size_t)i * STRIDE);
        float acc1 = 0.f;

        int j = beg;
        for (; j + 8 <= end; j += 8) {
            int s0 = __ldg(g_csr_src + j + 0);
            int s1 = __ldg(g_csr_src + j + 1);
            int s2 = __ldg(g_csr_src + j + 2);
            int s3 = __ldg(g_csr_src + j + 3);
            int s4 = __ldg(g_csr_src + j + 4);
            int s5 = __ldg(g_csr_src + j + 5);
            int s6 = __ldg(g_csr_src + j + 6);
            int s7 = __ldg(g_csr_src + j + 7);
            float c0 = __ldg(g_csr_cf + j + 0);
            float c1 = __ldg(g_csr_cf + j + 1);
            float c2 = __ldg(g_csr_cf + j + 2);
            float c3 = __ldg(g_csr_cf + j + 3);
            float c4 = __ldg(g_csr_cf + j + 4);
            float c5 = __ldg(g_csr_cf + j + 5);
            float c6 = __ldg(g_csr_cf + j + 6);
            float c7 = __ldg(g_csr_cf + j + 7);
            float v0 = __ldg(hf + (size_t)s0 * STRIDE);
            float v1 = __ldg(hf + (size_t)s1 * STRIDE);
            float v2 = __ldg(hf + (size_t)s2 * STRIDE);
            float v3 = __ldg(hf + (size_t)s3 * STRIDE);
            float v4 = __ldg(hf + (size_t)s4 * STRIDE);
            float v5 = __ldg(hf + (size_t)s5 * STRIDE);
            float v6 = __ldg(hf + (size_t)s6 * STRIDE);
            float v7 = __ldg(hf + (size_t)s7 * STRIDE);
            acc0 = fmaf(c0, v0, acc0); acc1 = fmaf(c1, v1, acc1);
            acc0 = fmaf(c2, v2, acc0); acc1 = fmaf(c3, v3, acc1);
            acc0 = fmaf(c4, v4, acc0); acc1 = fmaf(c5, v5, acc1);
            acc0 = fmaf(c6, v6, acc0); acc1 = fmaf(c7, v7, acc1);
        }
        for (; j < end; j++) {
            int s0 = __ldg(g_csr_src + j);
            float c0 = __ldg(g_csr_cf + j);
            acc0 = fmaf(c0, __ldg(hf + (size_t)s0 * STRIDE), acc0);
        }
        float acc = acc0 + acc1;
        uint32_t hi = f2tf(acc);
        size_t o = (size_t)i * STRIDE + foff + t;
        ah[o] = hi;
        al[o] = f2tf(acc - __uint_as_float(hi));
    }
}

// ---------------- split-tf32 TC GEMM, pre-split inputs -----------------------
__device__ __forceinline__ void mma_tf32(float4& d,
                                         uint32_t a0, uint32_t a1, uint32_t a2, uint32_t a3,
                                         uint32_t b0, uint32_t b1) {
    asm volatile("mma.sync.aligned.m16n8k8.row.col.f32.tf32.tf32.f32 "
                 "{%0,%1,%2,%3}, {%4,%5,%6,%7}, {%8,%9}, {%0,%1,%2,%3};"
                 : "+f"(d.x), "+f"(d.y), "+f"(d.z), "+f"(d.w)
                 : "r"(a0), "r"(a1), "r"(a2), "r"(a3), "r"(b0), "r"(b1));
}

#define TCSTRIDE 136

__global__ void __launch_bounds__(256) k_tcgemm(const uint32_t* __restrict__ Ahg,
                                                const uint32_t* __restrict__ Alg,
                                                const uint32_t* __restrict__ Bhg,
                                                const uint32_t* __restrict__ Blg,
                                                const float* __restrict__ bias,
                                                float* __restrict__ Cm,
                                                int M, int K, int Nc) {
    __shared__ uint32_t Ah[2][8][TCSTRIDE];
    __shared__ uint32_t Al[2][8][TCSTRIDE];
    __shared__ uint32_t Bh[2][8][TCSTRIDE];
    __shared__ uint32_t Bl[2][8][TCSTRIDE];

    const int tid = threadIdx.x;
    const int wid = tid >> 5;
    const int lane = tid & 31;
    const int q = lane >> 2;
    const int t4 = lane & 3;
    const int m0 = (wid & 3) * 32;
    const int n0 = (wid >> 2) * 64;

    const int rowBase = blockIdx.y * 128;
    const int colBase = blockIdx.x * 128;

    const int ar = tid >> 1;
    const int ac4 = (tid & 1) * 4;
    const int br = tid >> 5;
    const int bc4 = (tid & 31) * 4;
    const bool aok = (rowBase + ar) < M;
    const uint32_t* Ahp = Ahg + (size_t)(rowBase + ar) * K + ac4;
    const uint32_t* Alp = Alg + (size_t)(rowBase + ar) * K + ac4;
    const uint32_t* Bhp = Bhg + (size_t)br * Nc + colBase + bc4;
    const uint32_t* Blp = Blg + (size_t)br * Nc + colBase + bc4;

    float4 acc[2][8];
#pragma unroll
    for (int mi = 0; mi < 2; mi++)
#pragma unroll
        for (int ni = 0; ni < 8; ni++) acc[mi][ni] = make_float4(0.f, 0.f, 0.f, 0.f);

#define STORE_TILE(BUF, VAH, VAL, VBH, VBL)                                       \
    {                                                                             \
        Ah[BUF][ac4 + 0][ar] = (VAH).x; Ah[BUF][ac4 + 1][ar] = (VAH).y;           \
        Ah[BUF][ac4 + 2][ar] = (VAH).z; Ah[BUF][ac4 + 3][ar] = (VAH).w;           \
        Al[BUF][ac4 + 0][ar] = (VAL).x; Al[BUF][ac4 + 1][ar] = (VAL).y;           \
        Al[BUF][ac4 + 2][ar] = (VAL).z; Al[BUF][ac4 + 3][ar] = (VAL).w;           \
        Bh[BUF][br][bc4 + 0] = (VBH).x; Bh[BUF][br][bc4 + 1] = (VBH).y;           \
        Bh[BUF][br][bc4 + 2] = (VBH).z; Bh[BUF][br][bc4 + 3] = (VBH).w;           \
        Bl[BUF][br][bc4 + 0] = (VBL).x; Bl[BUF][br][bc4 + 1] = (VBL).y;           \
        Bl[BUF][br][bc4 + 2] = (VBL).z; Bl[BUF][br][bc4 + 3] = (VBL).w;           \
    }

#define LOAD_REGS(K0, VAH, VAL, VBH, VBL)                                         \
    uint4 VAH = make_uint4(0, 0, 0, 0), VAL = make_uint4(0, 0, 0, 0);             \
    if (aok) {                                                                    \
        VAH = *(const uint4*)(Ahp + (K0));                                        \
        VAL = *(const uint4*)(Alp + (K0));                                        \
    }                                                                             \
    uint4 VBH = *(const uint4*)(Bhp + (size_t)(K0) * Nc);                         \
    uint4 VBL = *(const uint4*)(Blp + (size_t)(K0) * Nc);

#define COMPUTE_TILE(BUF)                                                          \
    {                                                                              \
        uint32_t ah[2][4], al[2][4];                                               \
        _Pragma("unroll")                                                          \
        for (int mi = 0; mi < 2; mi++) {                                           \
            int mrow = m0 + mi * 16;                                               \
            ah[mi][0] = Ah[BUF][t4][mrow + q];                                     \
            ah[mi][1] = Ah[BUF][t4][mrow + q + 8];                                 \
            ah[mi][2] = Ah[BUF][t4 + 4][mrow + q];                                 \
            ah[mi][3] = Ah[BUF][t4 + 4][mrow + q + 8];                             \
            al[mi][0] = Al[BUF][t4][mrow + q];                                     \
            al[mi][1] = Al[BUF][t4][mrow + q + 8];                                 \
            al[mi][2] = Al[BUF][t4 + 4][mrow + q];                                 \
            al[mi][3] = Al[BUF][t4 + 4][mrow + q + 8];                             \
        }                                                                          \
        _Pragma("unroll")                                                          \
        for (int ni = 0; ni < 8; ni++) {                                           \
            int ncol = n0 + ni * 8 + q;                                            \
            uint32_t bh0 = Bh[BUF][t4][ncol];                                      \
            uint32_t bh1 = Bh[BUF][t4 + 4][ncol];                                  \
            uint32_t bl0 = Bl[BUF][t4][ncol];                                      \
            uint32_t bl1 = Bl[BUF][t4 + 4][ncol];                                  \
            _Pragma("unroll")                                                      \
            for (int mi = 0; mi < 2; mi++) {                                       \
                mma_tf32(acc[mi][ni], ah[mi][0], ah[mi][1], ah[mi][2], ah[mi][3],  \
                         bh0, bh1);                                                \
                mma_tf32(acc[mi][ni], ah[mi][0], ah[mi][1], ah[mi][2], ah[mi][3],  \
                         bl0, bl1);                                                \
                mma_tf32(acc[mi][ni], al[mi][0], al[mi][1], al[mi][2], al[mi][3],  \
                         bh0, bh1);                                                \
            }                                                                      \
        }                                                                          \
    }

    {
        LOAD_REGS(0, vah, val, vbh, vbl)
        STORE_TILE(0, vah, val, vbh, vbl)
    }
    __syncthreads();

    int buf = 0;
    for (int k0 = 8; k0 < K; k0 += 8) {
        LOAD_REGS(k0, vah, val, vbh, vbl)
        COMPUTE_TILE(buf)
        STORE_TILE(buf ^ 1, vah, val, vbh, vbl)
        __syncthreads();
        buf ^= 1;
    }
    COMPUTE_TILE(buf)

#pragma unroll
    for (int mi = 0; mi < 2; mi++) {
#pragma unroll
        for (int ni = 0; ni < 8; ni++) {
            int col = colBase + n0 + ni * 8 + 2 * t4;
            float bb0 = bias[col], bb1 = bias[col + 1];
            int r0 = rowBase + m0 + mi * 16 + q;
            int r1 = r0 + 8;
            float4 v = acc[mi][ni];
            float o0 = fmaxf(v.x + bb0, 0.f);
            float o1 = fmaxf(v.y + bb1, 0.f);
            float o2 = fmaxf(v.z + bb0, 0.f);
            float o3 = fmaxf(v.w + bb1, 0.f);
            if (r0 < M) *(float2*)(Cm + (size_t)r0 * Nc + col) = make_float2(o0, o1);
            if (r1 < M) *(float2*)(Cm + (size_t)r1 * Nc + col) = make_float2(o2, o3);
        }
    }
}

// ---------------- softmax + argmax: persistent grid-stride -------------------
__global__ void __launch_bounds__(256) k_softmax(const float* __restrict__ logits,
                                                 float* __restrict__ S) {
    int t = threadIdx.x;
    __shared__ float sv[256];
    __shared__ int   si[256];
    for (int i = blockIdx.x; i < NN; i += gridDim.x) {
        const float* row = logits + (size_t)i * CC;
        float v0 = row[t], v1 = row[t + 256];
        float bv = v0; int bi = t;
        if (v1 > bv) { bv = v1; bi = t + 256; }

        sv[t] = bv; si[t] = bi;
        __syncthreads();
        for (int s = 128; s > 0; s >>= 1) {
            if (t < s) {
                float ov = sv[t + s]; int oi = si[t + s];
                if (ov > sv[t] || (ov == sv[t] && oi < si[t])) { sv[t] = ov; si[t] = oi; }
            }
            __syncthreads();
        }
        float m = sv[0];
        if (t == 0) g_cluster[i] = si[0];
        __syncthreads();

        float e0 = expf(v0 - m), e1 = expf(v1 - m);
        sv[t] = e0 + e1;
        __syncthreads();
        for (int s = 128; s > 0; s >>= 1) {
            if (t < s) sv[t] += sv[t + s];
            __syncthreads();
        }
        float invsum = 1.0f / sv[0];
        S[(size_t)i * CC + t]       = e0 * invsum;
        S[(size_t)i * CC + t + 256] = e1 * invsum;
        __syncthreads();
    }
}

// ---------------- fused: hs (x@Ws) + intradeg --------------------------------
__global__ void k_hsintra(const float* __restrict__ x,
                          const float* __restrict__ Ws,
                          const int* __restrict__ ei) {
    int bid = blockIdx.x;
    int t = threadIdx.x;
    if (bid < HSB) {
        int g = bid * 256 + t;
        int w = g >> 5, lane = g & 31;
        if (w >= NN) return;
        float s = 0.f;
        for (int f = lane; f < FF; f += 32) s = fmaf(x[(size_t)w * FF + f], Ws[f], s);
#pragma unroll
        for (int off = 16; off > 0; off >>= 1) s += __shfl_down_sync(0xFFFFFFFF, s, off);
        if (lane == 0) g_hs[w] = s;
    } else {
        int e = (bid - HSB) * 256 + t;
        if (e >= EE) return;
        int s = ei[e], d = ei[EE + e];
        int cs = g_cluster[s], cd = g_cluster[d];
        if (cs == cd) {
            atomicAdd(&g_sdeg[d], 1);
            atomicAdd(&g_icnt[cs], 1);
        }
    }
}

__global__ void k_invs() {
    int i = blockIdx.x * blockDim.x + threadIdx.x;
    if (i < NN) g_invs[i] = rsqrtf((float)g_sdeg[i] + 1.0f);
}

__global__ void k_sagg(const int* __restrict__ ei) {
    int e = blockIdx.x * blockDim.x + threadIdx.x;
    if (e >= EE) return;
    int s = ei[e], d = ei[EE + e];
    if (g_cluster[s] == g_cluster[d])
        atomicAdd(&g_sagg[d], g_invs[s] * g_invs[d] * g_hs[s]);
}

__global__ void k_score(const float* __restrict__ bs) {
    int i = blockIdx.x * blockDim.x + threadIdx.x;
    if (i >= NN) return;
    float inv = g_invs[i];
    float v = g_sagg[i] + inv * inv * g_hs[i] + bs[0];
    float sc = tanhf(v);
    g_score[i] = sc;
    atomicMax(&g_segkey[g_cluster[i]], fkey(sc));
}

__global__ void k_segidx() {
    int i = blockIdx.x * blockDim.x + threadIdx.x;
    if (i >= NN) return;
    int c = g_cluster[i];
    float mx = fdec(g_segkey[c]);
    if (g_score[i] >= mx) atomicMin(&g_segidx[c], i);
}

// ---------------- fused: pool + adjacency ------------------------------------
__global__ void k_pooladj(const float* __restrict__ x,
                          const int* __restrict__ ei,
                          float* __restrict__ out) {
    int bid = blockIdx.x;
    int t = threadIdx.x;
    if (bid < CC) {
        if (t < 128) {
            int c = bid;
            bool ne = g_icnt[c] > 0;
            float alpha = ne ? fdec(g_segkey[c]) : 0.f;
            int idx = min(g_segidx[c], NN - 1);
            out[(size_t)c * FF + t] = x[(size_t)idx * FF + t] * alpha;
        }
    } else {
        int e = (bid - CC) * 256 + t;
        if (e >= EE) return;
        int cs = g_cluster[ei[e]], cd = g_cluster[ei[EE + e]];
        if (cs != cd && g_icnt[cs] > 0 && g_icnt[cd] > 0)
            out[OFF_ADJ + (size_t)cs * CC + cd] = 1.0f;
    }
}

// ---------------- launch ------------------------------------------------------
extern "C" void kernel_launch(void* const* d_in, const int* in_sizes, int n_in,
                              void* d_out, int out_size) {
    const float* x   = (const float*)d_in[0];
    const int*   ei  = (const int*)d_in[1];
    const float* W1  = (const float*)d_in[3];
    const float* b1  = (const float*)d_in[4];
    const float* W2  = (const float*)d_in[5];
    const float* b2  = (const float*)d_in[6];
    const float* W3  = (const float*)d_in[7];
    const float* b3  = (const float*)d_in[8];
    const float* Ws  = (const float*)d_in[9];
    const float* bs  = (const float*)d_in[10];
    float* out = (float*)d_out;

    // TRUE device addresses of all scratch symbols used as kernel args
    // (host array names decay to the host shadow; ATS serves that from host
    // memory over C2C at ~200 GB/s — the R14 10ms bug).
    void* p;
    cudaGetSymbolAddress(&p, g_h);   float*    gh  = (float*)p;
    cudaGetSymbolAddress(&p, g_ah);  uint32_t* gah = (uint32_t*)p;
    cudaGetSymbolAddress(&p, g_al);  uint32_t* gal = (uint32_t*)p;
    cudaGetSymbolAddress(&p, g_wh);  uint32_t* gwh = (uint32_t*)p;
    cudaGetSymbolAddress(&p, g_wl);  uint32_t* gwl = (uint32_t*)p;

    const int NB = (NN + 255) / 256;
    const int PG128 = 148 * 16;
    const int PG256 = 148 * 8;

    k_initdeg<<<INITB + NB, 256>>>(out);
    k_deg<<<EB, 256>>>(ei);
    k_scan<<<1, 1024>>>();
    k_fill<<<EB, 256>>>(ei);
    k_wsplit<<<(WTOT + 255) / 256, 256>>>(W1, W2, W3, gwh, gwl);

    // layer 1: agg(x) -> split acts; gemm1
    k_aggs<128><<<PG128, 128>>>(x, gah, gal, 0);
    {
        dim3 g(HH / 128, (NN + 127) / 128);
        k_tcgemm<<<g, 256>>>(gah, gal, gwh + WOFF1, gwl + WOFF1, b1, gh, NN, FF, HH);
    }
    // layer 2
    k_aggs<256><<<PG128, 128>>>(gh, gah, gal, 0);
    k_aggs<256><<<PG128, 128>>>(gh, gah, gal, 128);
    {
        dim3 g(HH / 128, (NN + 127) / 128);
        k_tcgemm<<<g, 256>>>(gah, gal, gwh + WOFF2, gwl + WOFF2, b2, gh, NN, HH, HH);
    }
    // layer 3
    k_aggs<256><<<PG128, 128>>>(gh, gah, gal, 0);
    k_aggs<256><<<PG128, 128>>>(gh, gah, gal, 128);
    {
        dim3 g(CC / 128, (NN + 127) / 128);
        k_tcgemm<<<g, 256>>>(gah, gal, gwh + WOFF3, gwl + WOFF3, b3, gh, NN, HH, CC);
    }

    k_softmax<<<PG256, 256>>>(gh, out + OFF_S);

    k_hsintra<<<HSB + EB, 256>>>(x, Ws, ei);
    k_invs<<<NB, 256>>>();
    k_sagg<<<EB, 256>>>(ei);
    k_score<<<NB, 256>>>(bs);
    k_segidx<<<NB, 256>>>();
    k_pooladj<<<CC + EB, 256>>>(x, ei, out);

    (void)in_sizes; (void)n_in; (void)out_size;
}

// round 17
// speedup vs baseline: 1.0255x; 1.0255x over previous
#include <cuda_runtime.h>
#include <math.h>
#include <stdint.h>

#define NN 50000
#define FF 128
#define CC 512
#define EE 800000
#define HH 256

// Output layout: new_x [C,F], new_adj [C,C], new_batch [C], S [N,C]
#define OFF_ADJ   (CC*FF)
#define OFF_BATCH (OFF_ADJ + CC*CC)
#define OFF_S     (OFF_BATCH + CC)

#define EB ((EE + 255) / 256)
#define HSB ((NN * 32 + 255) / 256)
#define INITB 512

// weight split offsets (elements)
#define WOFF1 0
#define WOFF2 (FF*HH)
#define WOFF3 (WOFF2 + HH*HH)
#define WTOT  (WOFF3 + HH*CC)
#define WB ((WTOT + 255) / 256)

// ---------------- scratch ----------------------------------------------------
__device__ __align__(16) float    g_h[(size_t)NN * CC];
__device__ __align__(16) uint32_t g_ah[(size_t)NN * HH];
__device__ __align__(16) uint32_t g_al[(size_t)NN * HH];
__device__ __align__(16) uint32_t g_wh[WTOT];
__device__ __align__(16) uint32_t g_wl[WTOT];
__device__ float g_inv[NN];
__device__ int   g_deg[NN];          // zero-invariant: re-zeroed by k_fill
__device__ int   g_off[NN + 1];
__device__ int   g_cur[NN];
__device__ int   g_csr_src[EE];
__device__ float g_csr_cf[EE];
__device__ int   g_cluster[NN];
__device__ float g_hs[NN];
__device__ int   g_sdeg[NN];
__device__ float g_invs[NN];
__device__ float g_sagg[NN];
__device__ float g_score[NN];
__device__ int   g_icnt[CC];
__device__ int   g_segkey[CC];
__device__ int   g_segidx[CC];

__device__ __forceinline__ int fkey(float f) {
    int b = __float_as_int(f);
    return b < 0 ? (b ^ 0x7FFFFFFF) : b;
}
__device__ __forceinline__ float fdec(int k) {
    return __int_as_float(k < 0 ? (k ^ 0x7FFFFFFF) : k);
}
__device__ __forceinline__ uint32_t f2tf(float f) {
    uint32_t r;
    asm("cvt.rna.tf32.f32 %0, %1;" : "=r"(r) : "f"(f));
    return r;
}
__device__ __forceinline__ void cp16(void* smem, const void* gmem) {
    uint32_t s = (uint32_t)__cvta_generic_to_shared(smem);
    asm volatile("cp.async.cg.shared.global [%0], [%1], 16;" :: "r"(s), "l"(gmem));
}
#define CP_COMMIT() asm volatile("cp.async.commit_group;")
#define CP_WAIT(N)  asm volatile("cp.async.wait_group %0;" :: "n"(N))

// ---------------- fused init + degree histogram + weight split ---------------
// g_deg is zero on entry (static init on first call; k_fill re-zeroes after
// the scan consumes it on every call) so histogram blocks can run concurrently
// with the init blocks (disjoint arrays).
__global__ void k_init_all(float* out,
                           const int* __restrict__ ei,
                           const float* __restrict__ W1,
                           const float* __restrict__ W2,
                           const float* __restrict__ W3,
                           uint32_t* __restrict__ wh,
                           uint32_t* __restrict__ wl) {
    int bid = blockIdx.x;
    int t = threadIdx.x;
    if (bid < INITB) {
        int i = bid * 256 + t;
        int stride = INITB * 256;
        for (int j = i; j < NN; j += stride) { g_sdeg[j] = 0; g_sagg[j] = 0.f; }
        for (int j = i; j < CC; j += stride) {
            g_icnt[j] = 0; g_segkey[j] = (int)0x80000000; g_segidx[j] = NN;
            out[OFF_BATCH + j] = 0.f;
        }
        for (int j = i; j < CC * CC; j += stride) out[OFF_ADJ + j] = 0.f;
    } else if (bid < INITB + EB) {
        int e = (bid - INITB) * 256 + t;
        if (e < EE) atomicAdd(&g_deg[ei[EE + e]], 1);
    } else {
        int i = (bid - INITB - EB) * 256 + t;
        if (i < WTOT) {
            float v;
            if (i < WOFF2)      v = W1[i - WOFF1];
            else if (i < WOFF3) v = W2[i - WOFF2];
            else                v = W3[i - WOFF3];
            uint32_t h = f2tf(v);
            wh[i] = h;
            wl[i] = f2tf(v - __uint_as_float(h));
        }
    }
}

// single block: exclusive scan + inv + cur
__global__ void __launch_bounds__(1024) k_scan() {
    __shared__ int ssum[1024];
    int t = threadIdx.x;
    const int chunk = (NN + 1023) / 1024;
    int b = t * chunk, e = min(b + chunk, NN);
    int s = 0;
    for (int i = b; i < e; i++) s += g_deg[i];
    ssum[t] = s;
    __syncthreads();
    for (int off = 1; off < 1024; off <<= 1) {
        int v = (t >= off) ? ssum[t - off] : 0;
        __syncthreads();
        ssum[t] += v;
        __syncthreads();
    }
    int run = (t > 0) ? ssum[t - 1] : 0;
    for (int i = b; i < e; i++) {
        int d = g_deg[i];
        g_off[i] = run;
        g_cur[i] = run;
        g_inv[i] = rsqrtf((float)d + 1.0f);
        run += d;
    }
    if (t == 1023) g_off[NN] = ssum[1023];
}

// fill CSR; also restores the g_deg zero-invariant for the next call
__global__ void k_fill(const int* __restrict__ ei) {
    int e = blockIdx.x * blockDim.x + threadIdx.x;
    if (e < NN) g_deg[e] = 0;
    if (e >= EE) return;
    int s = ei[e], d = ei[EE + e];
    int p = atomicAdd(&g_cur[d], 1);
    g_csr_src[p] = s;
    g_csr_cf[p] = g_inv[s] * g_inv[d];
}

// ---------------- aggregation: 128-wide slice, writes split tf32 -------------
template <int STRIDE>
__global__ void __launch_bounds__(128) k_aggs(const float* __restrict__ h,
                                              uint32_t* __restrict__ ah,
                                              uint32_t* __restrict__ al,
                                              int foff) {
    int t = threadIdx.x;
    const float* hf = h + foff + t;
    for (int i = blockIdx.x; i < NN; i += gridDim.x) {
        int beg = g_off[i], end = g_off[i + 1];
        float inv = g_inv[i];
        float acc0 = inv * inv * __ldg(hf + (size_t)i * STRIDE);
        float acc1 = 0.f;

        int j = beg;
        for (; j + 8 <= end; j += 8) {
            int s0 = __ldg(g_csr_src + j + 0);
            int s1 = __ldg(g_csr_src + j + 1);
            int s2 = __ldg(g_csr_src + j + 2);
            int s3 = __ldg(g_csr_src + j + 3);
            int s4 = __ldg(g_csr_src + j + 4);
            int s5 = __ldg(g_csr_src + j + 5);
            int s6 = __ldg(g_csr_src + j + 6);
            int s7 = __ldg(g_csr_src + j + 7);
            float c0 = __ldg(g_csr_cf + j + 0);
            float c1 = __ldg(g_csr_cf + j + 1);
            float c2 = __ldg(g_csr_cf + j + 2);
            float c3 = __ldg(g_csr_cf + j + 3);
            float c4 = __ldg(g_csr_cf + j + 4);
            float c5 = __ldg(g_csr_cf + j + 5);
            float c6 = __ldg(g_csr_cf + j + 6);
            float c7 = __ldg(g_csr_cf + j + 7);
            float v0 = __ldg(hf + (size_t)s0 * STRIDE);
            float v1 = __ldg(hf + (size_t)s1 * STRIDE);
            float v2 = __ldg(hf + (size_t)s2 * STRIDE);
            float v3 = __ldg(hf + (size_t)s3 * STRIDE);
            float v4 = __ldg(hf + (size_t)s4 * STRIDE);
            float v5 = __ldg(hf + (size_t)s5 * STRIDE);
            float v6 = __ldg(hf + (size_t)s6 * STRIDE);
            float v7 = __ldg(hf + (size_t)s7 * STRIDE);
            acc0 = fmaf(c0, v0, acc0); acc1 = fmaf(c1, v1, acc1);
            acc0 = fmaf(c2, v2, acc0); acc1 = fmaf(c3, v3, acc1);
            acc0 = fmaf(c4, v4, acc0); acc1 = fmaf(c5, v5, acc1);
            acc0 = fmaf(c6, v6, acc0); acc1 = fmaf(c7, v7, acc1);
        }
        for (; j < end; j++) {
            int s0 = __ldg(g_csr_src + j);
            float c0 = __ldg(g_csr_cf + j);
            acc0 = fmaf(c0, __ldg(hf + (size_t)s0 * STRIDE), acc0);
        }
        float acc = acc0 + acc1;
        uint32_t hi = f2tf(acc);
        size_t o = (size_t)i * STRIDE + foff + t;
        ah[o] = hi;
        al[o] = f2tf(acc - __uint_as_float(hi));
    }
}

// ---------------- split-tf32 TC GEMM, cp.async 2-stage pipeline --------------
__device__ __forceinline__ void mma_tf32(float4& d,
                                         uint32_t a0, uint32_t a1, uint32_t a2, uint32_t a3,
                                         uint32_t b0, uint32_t b1) {
    asm volatile("mma.sync.aligned.m16n8k8.row.col.f32.tf32.tf32.f32 "
                 "{%0,%1,%2,%3}, {%4,%5,%6,%7}, {%8,%9}, {%0,%1,%2,%3};"
                 : "+f"(d.x), "+f"(d.y), "+f"(d.z), "+f"(d.w)
                 : "r"(a0), "r"(a1), "r"(a2), "r"(a3), "r"(b0), "r"(b1));
}

#define APAD 12      // A smem row stride (words): 48B = 16B multiple, bank-conflict-free
#define BSTR 136     // B smem row stride (words): 544B = 16B multiple

__global__ void __launch_bounds__(256) k_tcgemm(const uint32_t* __restrict__ Ahg,
                                                const uint32_t* __restrict__ Alg,
                                                const uint32_t* __restrict__ Bhg,
                                                const uint32_t* __restrict__ Blg,
                                                const float* __restrict__ bias,
                                                float* __restrict__ Cm,
                                                int M, int K, int Nc) {
    __shared__ uint32_t Ah[2][128][APAD];
    __shared__ uint32_t Al[2][128][APAD];
    __shared__ uint32_t Bh[2][8][BSTR];
    __shared__ uint32_t Bl[2][8][BSTR];

    const int tid = threadIdx.x;
    const int wid = tid >> 5;
    const int lane = tid & 31;
    const int q = lane >> 2;
    const int t4 = lane & 3;
    const int m0 = (wid & 3) * 32;
    const int n0 = (wid >> 2) * 64;

    const int rowBase = blockIdx.y * 128;
    const int colBase = blockIdx.x * 128;

    // cp.async loader mapping: A row ar (0..127), k-offset ac4 (0 or 4);
    // B row br (0..7), col-offset bc4 (0..124)
    const int ar = tid >> 1;
    const int ac4 = (tid & 1) * 4;
    const int br = tid >> 5;
    const int bc4 = (tid & 31) * 4;
    const int arow = min(rowBase + ar, M - 1);   // clamp OOB rows (results unused)
    const uint32_t* Ahp = Ahg + (size_t)arow * K + ac4;
    const uint32_t* Alp = Alg + (size_t)arow * K + ac4;
    const uint32_t* Bhp = Bhg + (size_t)br * Nc + colBase + bc4;
    const uint32_t* Blp = Blg + (size_t)br * Nc + colBase + bc4;

    float4 acc[2][8];
#pragma unroll
    for (int mi = 0; mi < 2; mi++)
#pragma unroll
        for (int ni = 0; ni < 8; ni++) acc[mi][ni] = make_float4(0.f, 0.f, 0.f, 0.f);

#define PF(BUF, K0)                                                     \
    {                                                                   \
        cp16(&Ah[BUF][ar][ac4], Ahp + (K0));                            \
        cp16(&Al[BUF][ar][ac4], Alp + (K0));                            \
        cp16(&Bh[BUF][br][bc4], Bhp + (size_t)(K0) * Nc);               \
        cp16(&Bl[BUF][br][bc4], Blp + (size_t)(K0) * Nc);               \
    }

#define COMPUTE_TILE(BUF)                                                          \
    {                                                                              \
        uint32_t ah[2][4], al[2][4];                                               \
        _Pragma("unroll")                                                          \
        for (int mi = 0; mi < 2; mi++) {                                           \
            int mrow = m0 + mi * 16;                                               \
            ah[mi][0] = Ah[BUF][mrow + q][t4];                                     \
            ah[mi][1] = Ah[BUF][mrow + q + 8][t4];                                 \
            ah[mi][2] = Ah[BUF][mrow + q][t4 + 4];                                 \
            ah[mi][3] = Ah[BUF][mrow + q + 8][t4 + 4];                             \
            al[mi][0] = Al[BUF][mrow + q][t4];                                     \
            al[mi][1] = Al[BUF][mrow + q + 8][t4];                                 \
            al[mi][2] = Al[BUF][mrow + q][t4 + 4];                                 \
            al[mi][3] = Al[BUF][mrow + q + 8][t4 + 4];                             \
        }                                                                          \
        _Pragma("unroll")                                                          \
        for (int ni = 0; ni < 8; ni++) {                                           \
            int ncol = n0 + ni * 8 + q;                                            \
            uint32_t bh0 = Bh[BUF][t4][ncol];                                      \
            uint32_t bh1 = Bh[BUF][t4 + 4][ncol];                                  \
            uint32_t bl0 = Bl[BUF][t4][ncol];                                      \
            uint32_t bl1 = Bl[BUF][t4 + 4][ncol];                                  \
            _Pragma("unroll")                                                      \
            for (int mi = 0; mi < 2; mi++) {                                       \
                mma_tf32(acc[mi][ni], ah[mi][0], ah[mi][1], ah[mi][2], ah[mi][3],  \
                         bh0, bh1);                                                \
                mma_tf32(acc[mi][ni], ah[mi][0], ah[mi][1], ah[mi][2], ah[mi][3],  \
                         bl0, bl1);                                                \
                mma_tf32(acc[mi][ni], al[mi][0], al[mi][1], al[mi][2], al[mi][3],  \
                         bh0, bh1);                                                \
            }                                                                      \
        }                                                                          \
    }

    PF(0, 0)
    CP_COMMIT();

    const int T = K >> 3;
    int buf = 0;
    for (int s = 0; s < T; s++) {
        CP_WAIT(0);
        __syncthreads();
        if (s + 1 < T) {
            PF(buf ^ 1, (s + 1) * 8)
            CP_COMMIT();
        }
        COMPUTE_TILE(buf)
        buf ^= 1;
    }

#pragma unroll
    for (int mi = 0; mi < 2; mi++) {
#pragma unroll
        for (int ni = 0; ni < 8; ni++) {
            int col = colBase + n0 + ni * 8 + 2 * t4;
            float bb0 = bias[col], bb1 = bias[col + 1];
            int r0 = rowBase + m0 + mi * 16 + q;
            int r1 = r0 + 8;
            float4 v = acc[mi][ni];
            float o0 = fmaxf(v.x + bb0, 0.f);
            float o1 = fmaxf(v.y + bb1, 0.f);
            float o2 = fmaxf(v.z + bb0, 0.f);
            float o3 = fmaxf(v.w + bb1, 0.f);
            if (r0 < M) *(float2*)(Cm + (size_t)r0 * Nc + col) = make_float2(o0, o1);
            if (r1 < M) *(float2*)(Cm + (size_t)r1 * Nc + col) = make_float2(o2, o3);
        }
    }
}

// ---------------- softmax + argmax: persistent grid-stride -------------------
__global__ void __launch_bounds__(256) k_softmax(const float* __restrict__ logits,
                                                 float* __restrict__ S) {
    int t = threadIdx.x;
    __shared__ float sv[256];
    __shared__ int   si[256];
    for (int i = blockIdx.x; i < NN; i += gridDim.x) {
        const float* row = logits + (size_t)i * CC;
        float v0 = row[t], v1 = row[t + 256];
        float bv = v0; int bi = t;
        if (v1 > bv) { bv = v1; bi = t + 256; }

        sv[t] = bv; si[t] = bi;
        __syncthreads();
        for (int s = 128; s > 0; s >>= 1) {
            if (t < s) {
                float ov = sv[t + s]; int oi = si[t + s];
                if (ov > sv[t] || (ov == sv[t] && oi < si[t])) { sv[t] = ov; si[t] = oi; }
            }
            __syncthreads();
        }
        float m = sv[0];
        if (t == 0) g_cluster[i] = si[0];
        __syncthreads();

        float e0 = expf(v0 - m), e1 = expf(v1 - m);
        sv[t] = e0 + e1;
        __syncthreads();
        for (int s = 128; s > 0; s >>= 1) {
            if (t < s) sv[t] += sv[t + s];
            __syncthreads();
        }
        float invsum = 1.0f / sv[0];
        S[(size_t)i * CC + t]       = e0 * invsum;
        S[(size_t)i * CC + t + 256] = e1 * invsum;
        __syncthreads();
    }
}

// ---------------- fused: hs (x@Ws) + intradeg --------------------------------
__global__ void k_hsintra(const float* __restrict__ x,
                          const float* __restrict__ Ws,
                          const int* __restrict__ ei) {
    int bid = blockIdx.x;
    int t = threadIdx.x;
    if (bid < HSB) {
        int g = bid * 256 + t;
        int w = g >> 5, lane = g & 31;
        if (w >= NN) return;
        float s = 0.f;
        for (int f = lane; f < FF; f += 32) s = fmaf(x[(size_t)w * FF + f], Ws[f], s);
#pragma unroll
        for (int off = 16; off > 0; off >>= 1) s += __shfl_down_sync(0xFFFFFFFF, s, off);
        if (lane == 0) g_hs[w] = s;
    } else {
        int e = (bid - HSB) * 256 + t;
        if (e >= EE) return;
        int s = ei[e], d = ei[EE + e];
        int cs = g_cluster[s], cd = g_cluster[d];
        if (cs == cd) {
            atomicAdd(&g_sdeg[d], 1);
            atomicAdd(&g_icnt[cs], 1);
        }
    }
}

__global__ void k_invs() {
    int i = blockIdx.x * blockDim.x + threadIdx.x;
    if (i < NN) g_invs[i] = rsqrtf((float)g_sdeg[i] + 1.0f);
}

__global__ void k_sagg(const int* __restrict__ ei) {
    int e = blockIdx.x * blockDim.x + threadIdx.x;
    if (e >= EE) return;
    int s = ei[e], d = ei[EE + e];
    if (g_cluster[s] == g_cluster[d])
        atomicAdd(&g_sagg[d], g_invs[s] * g_invs[d] * g_hs[s]);
}

__global__ void k_score(const float* __restrict__ bs) {
    int i = blockIdx.x * blockDim.x + threadIdx.x;
    if (i >= NN) return;
    float inv = g_invs[i];
    float v = g_sagg[i] + inv * inv * g_hs[i] + bs[0];
    float sc = tanhf(v);
    g_score[i] = sc;
    atomicMax(&g_segkey[g_cluster[i]], fkey(sc));
}

__global__ void k_segidx() {
    int i = blockIdx.x * blockDim.x + threadIdx.x;
    if (i >= NN) return;
    int c = g_cluster[i];
    float mx = fdec(g_segkey[c]);
    if (g_score[i] >= mx) atomicMin(&g_segidx[c], i);
}

// ---------------- fused: pool + adjacency ------------------------------------
__global__ void k_pooladj(const float* __restrict__ x,
                          const int* __restrict__ ei,
                          float* __restrict__ out) {
    int bid = blockIdx.x;
    int t = threadIdx.x;
    if (bid < CC) {
        if (t < 128) {
            int c = bid;
            bool ne = g_icnt[c] > 0;
            float alpha = ne ? fdec(g_segkey[c]) : 0.f;
            int idx = min(g_segidx[c], NN - 1);
            out[(size_t)c * FF + t] = x[(size_t)idx * FF + t] * alpha;
        }
    } else {
        int e = (bid - CC) * 256 + t;
        if (e >= EE) return;
        int cs = g_cluster[ei[e]], cd = g_cluster[ei[EE + e]];
        if (cs != cd && g_icnt[cs] > 0 && g_icnt[cd] > 0)
            out[OFF_ADJ + (size_t)cs * CC + cd] = 1.0f;
    }
}

// ---------------- launch ------------------------------------------------------
extern "C" void kernel_launch(void* const* d_in, const int* in_sizes, int n_in,
                              void* d_out, int out_size) {
    const float* x   = (const float*)d_in[0];
    const int*   ei  = (const int*)d_in[1];
    const float* W1  = (const float*)d_in[3];
    const float* b1  = (const float*)d_in[4];
    const float* W2  = (const float*)d_in[5];
    const float* b2  = (const float*)d_in[6];
    const float* W3  = (const float*)d_in[7];
    const float* b3  = (const float*)d_in[8];
    const float* Ws  = (const float*)d_in[9];
    const float* bs  = (const float*)d_in[10];
    float* out = (float*)d_out;

    // TRUE device addresses of scratch symbols (host-decayed names hit the
    // host shadow via ATS at C2C speed — the R14 lesson).
    void* p;
    cudaGetSymbolAddress(&p, g_h);   float*    gh  = (float*)p;
    cudaGetSymbolAddress(&p, g_ah);  uint32_t* gah = (uint32_t*)p;
    cudaGetSymbolAddress(&p, g_al);  uint32_t* gal = (uint32_t*)p;
    cudaGetSymbolAddress(&p, g_wh);  uint32_t* gwh = (uint32_t*)p;
    cudaGetSymbolAddress(&p, g_wl);  uint32_t* gwl = (uint32_t*)p;

    const int NB = (NN + 255) / 256;
    const int PG128 = 148 * 16;
    const int PG256 = 148 * 8;

    k_init_all<<<INITB + EB + WB, 256>>>(out, ei, W1, W2, W3, gwh, gwl);  // 0
    k_scan<<<1, 1024>>>();                                                // 1
    k_fill<<<EB, 256>>>(ei);                                              // 2
    k_aggs<128><<<PG128, 128>>>(x, gah, gal, 0);                          // 3 [sentinel]
    {
        dim3 g(HH / 128, (NN + 127) / 128);
        k_tcgemm<<<g, 256>>>(gah, gal, gwh + WOFF1, gwl + WOFF1, b1, gh, NN, FF, HH);
    }
    k_aggs<256><<<PG128, 128>>>(gh, gah, gal, 0);
    k_aggs<256><<<PG128, 128>>>(gh, gah, gal, 128);
    {
        dim3 g(HH / 128, (NN + 127) / 128);
        k_tcgemm<<<g, 256>>>(gah, gal, gwh + WOFF2, gwl + WOFF2, b2, gh, NN, HH, HH);
    }
    k_aggs<256><<<PG128, 128>>>(gh, gah, gal, 0);
    k_aggs<256><<<PG128, 128>>>(gh, gah, gal, 128);
    {
        dim3 g(CC / 128, (NN + 127) / 128);
        k_tcgemm<<<g, 256>>>(gah, gal, gwh + WOFF3, gwl + WOFF3, b3, gh, NN, HH, CC);
    }

    k_softmax<<<PG256, 256>>>(gh, out + OFF_S);

    k_hsintra<<<HSB + EB, 256>>>(x, Ws, ei);
    k_invs<<<NB, 256>>>();
    k_sagg<<<EB, 256>>>(ei);
    k_score<<<NB, 256>>>(bs);
    k_segidx<<<NB, 256>>>();
    k_pooladj<<<CC + EB, 256>>>(x, ei, out);

    (void)in_sizes; (void)n_in; (void)out_size;
}